// round 14
// baseline (speedup 1.0000x reference)
#include <cuda_runtime.h>
#include <cuda_fp16.h>
#include <cstdint>
#include <math.h>

// DoubleNet (sm_103, HMMA): partial fusion. Per 64-sample m-block, TWO CTAs:
//   x=0 (alloc): 4 layers -> mat staged in SMEM -> in-CTA Sinkhorn -> allocs+psum
//   x=1 (pay):   3 layers -> payment head -> frac
// Tiny final kernel: payments = frac * psum.
// fp16 2-way-split HMMA products. B=32768, D=256, H=128, A=I=16, EPS=0.1.

#define MAXB 32768

__device__ __half g_wt[327680];     // per-weight: hi plane [N*K], lo plane [N*K]
__device__ float  g_frac[MAXB * 16];
__device__ float  g_psum[MAXB * 16];

// offsets in halves
#define OFF_AW0 0
#define OFF_AW1 65536
#define OFF_AW2 98304
#define OFF_AW3 131072
#define OFF_PW0 196608
#define OFF_PW1 262144
#define OFF_PW2 294912

// ---------------- helpers ----------------------------------------------------
__device__ __forceinline__ uint32_t smem_u32(const void* p) {
    uint32_t a;
    asm("{ .reg .u64 t; cvta.to.shared.u64 t, %1; cvt.u32.u64 %0, t; }"
        : "=r"(a) : "l"(p));
    return a;
}
__device__ __forceinline__ void split2(float x0, float x1, uint32_t& hw, uint32_t& lw) {
    __half h0 = __float2half_rn(x0), h1 = __float2half_rn(x1);
    __half l0 = __float2half_rn(x0 - __half2float(h0));
    __half l1 = __float2half_rn(x1 - __half2float(h1));
    hw = (uint32_t)__half_as_ushort(h0) | ((uint32_t)__half_as_ushort(h1) << 16);
    lw = (uint32_t)__half_as_ushort(l0) | ((uint32_t)__half_as_ushort(l1) << 16);
}
__device__ __forceinline__ void mma16816_f(float* d, const uint32_t* a, const uint32_t* b) {
    asm volatile(
        "mma.sync.aligned.m16n8k16.row.col.f32.f16.f16.f32 "
        "{%0,%1,%2,%3}, {%4,%5,%6,%7}, {%8,%9}, {%0,%1,%2,%3};"
        : "+f"(d[0]), "+f"(d[1]), "+f"(d[2]), "+f"(d[3])
        : "r"(a[0]), "r"(a[1]), "r"(a[2]), "r"(a[3]), "r"(b[0]), "r"(b[1]));
}
__device__ __forceinline__ void mma16816_h(uint32_t* d, const uint32_t* a, const uint32_t* b) {
    asm volatile(
        "mma.sync.aligned.m16n8k16.row.col.f16.f16.f16.f16 "
        "{%0,%1}, {%2,%3,%4,%5}, {%6,%7}, {%0,%1};"
        : "+r"(d[0]), "+r"(d[1])
        : "r"(a[0]), "r"(a[1]), "r"(a[2]), "r"(a[3]), "r"(b[0]), "r"(b[1]));
}
#define LDSM4(R, addr) \
    asm volatile("ldmatrix.sync.aligned.m8n8.x4.shared.b16 {%0,%1,%2,%3}, [%4];" \
                 : "=r"((R)[0]), "=r"((R)[1]), "=r"((R)[2]), "=r"((R)[3]) : "r"(addr))
#define CP_ASYNC16(dst, src) \
    asm volatile("cp.async.cg.shared.global [%0], [%1], 16;" :: "r"(dst), "l"(src))
#define CP_COMMIT() asm volatile("cp.async.commit_group;")
#define CP_WAIT0()  asm volatile("cp.async.wait_group 0;")

// ---------------- weight packing: SMEM tile transpose ------------------------
__global__ void pack_w_tile(const float* __restrict__ aw0, const float* __restrict__ aw1,
                            const float* __restrict__ aw2, const float* __restrict__ aw3,
                            const float* __restrict__ pw0, const float* __restrict__ pw1,
                            const float* __restrict__ pw2, __half* __restrict__ wt)
{
    const float* src; int K, N, off;
    switch (blockIdx.y) {
        case 0: src = aw0; K = 256; N = 128; off = OFF_AW0; break;
        case 1: src = aw1; K = 128; N = 128; off = OFF_AW1; break;
        case 2: src = aw2; K = 128; N = 128; off = OFF_AW2; break;
        case 3: src = aw3; K = 128; N = 256; off = OFF_AW3; break;
        case 4: src = pw0; K = 256; N = 128; off = OFF_PW0; break;
        case 5: src = pw1; K = 128; N = 128; off = OFF_PW1; break;
        default: src = pw2; K = 128; N = 128; off = OFF_PW2; break;
    }
    int tiles_n = N / 32;
    int tile = blockIdx.x;
    if (tile >= (K / 32) * tiles_n) return;
    int k0 = (tile / tiles_n) * 32, n0 = (tile % tiles_n) * 32;

    __shared__ float t[32][33];
    int c = threadIdx.x & 31, r8 = threadIdx.x >> 5;
#pragma unroll
    for (int j = 0; j < 4; j++) {
        int r = r8 + j * 8;
        t[r][c] = src[(size_t)(k0 + r) * N + n0 + c];
    }
    __syncthreads();
#pragma unroll
    for (int j = 0; j < 4; j++) {
        int n = r8 + j * 8;
        float v = t[c][n];
        __half h = __float2half_rn(v);
        size_t o = (size_t)(n0 + n) * K + k0 + c;
        wt[off + o]                 = h;
        wt[off + (size_t)N * K + o] = __float2half_rn(v - __half2float(h));
    }
}

// ---------------- SMEM layout ------------------------------------------------
#define ROWB   272
#define APLANE 17408
#define SM_AHI 0
#define SM_ALO 17408
#define SM_BHI 34816
#define SM_BLO 69632
#define SMEM_BYTES 104448
#define STG_ROW 260   // f32 words per staged mat row

__device__ __forceinline__ void cpa128(uint32_t dst, const __half* __restrict__ src,
                                       int stride_h, int tid) {
#pragma unroll
    for (int j = 0; j < 8; j++) {
        int lin = j * 256 + tid;
        int row = lin >> 4;
        int q   = lin & 15;
        CP_ASYNC16(dst + row * ROWB + q * 16, src + row * stride_h + q * 8);
    }
}
__device__ __forceinline__ void load_w(uint32_t sb, const __half* __restrict__ whi,
                                       const __half* __restrict__ wlo,
                                       int noff, int koff, int K, int tid) {
    cpa128(sb + SM_BHI, whi + (size_t)noff * K + koff, K, tid);
    cpa128(sb + SM_BLO, wlo + (size_t)noff * K + koff, K, tid);
    CP_COMMIT();
}
__device__ __forceinline__ void load_f32_pair(char* hi, char* lo,
                                              const float4* __restrict__ src,
                                              int stride16, int tid) {
#pragma unroll
    for (int j = 0; j < 8; j++) {
        int lin = j * 256 + tid;
        int row = lin >> 5;
        int g   = lin & 31;
        float4 v = src[row * stride16 + g];
        uint32_t h0, l0, h1, l1;
        split2(v.x, v.y, h0, l0);
        split2(v.z, v.w, h1, l1);
        int off = row * ROWB + g * 8;
        *(uint2*)(hi + off) = make_uint2(h0, h1);
        *(uint2*)(lo + off) = make_uint2(l0, l1);
    }
}

// ---------------- MMA tile ----------------------------------------------------
struct Acc {
    float    f[2][4][4];
    uint32_t h[2][4][2];
    __device__ __forceinline__ void zero() {
#pragma unroll
        for (int i = 0; i < 2; i++)
#pragma unroll
            for (int j = 0; j < 4; j++) {
#pragma unroll
                for (int q = 0; q < 4; q++) f[i][j][q] = 0.f;
                h[i][j][0] = 0u; h[i][j][1] = 0u;
            }
    }
    __device__ __forceinline__ void merge() {
#pragma unroll
        for (int i = 0; i < 2; i++)
#pragma unroll
            for (int j = 0; j < 4; j++) {
                float2 f0 = __half22float2(*reinterpret_cast<__half2*>(&h[i][j][0]));
                float2 f1 = __half22float2(*reinterpret_cast<__half2*>(&h[i][j][1]));
                f[i][j][0] += f0.x; f[i][j][1] += f0.y;
                f[i][j][2] += f1.x; f[i][j][3] += f1.y;
            }
    }
};

__device__ __forceinline__ void mma_phase(Acc& A, uint32_t aBase, uint32_t bBase) {
#pragma unroll
    for (int kk = 0; kk < 8; kk++) {
        uint32_t ahi[2][4], alo[2][4];
#pragma unroll
        for (int i = 0; i < 2; i++) {
            LDSM4(ahi[i], aBase + i * (16 * ROWB) + kk * 32);
            LDSM4(alo[i], aBase + APLANE + i * (16 * ROWB) + kk * 32);
        }
        uint32_t bhi[4][2], blo[4][2];
#pragma unroll
        for (int jj = 0; jj < 2; jj++) {
            uint32_t r[4];
            LDSM4(r, bBase + jj * (16 * ROWB) + kk * 32);
            bhi[2 * jj][0] = r[0]; bhi[2 * jj + 1][0] = r[1];
            bhi[2 * jj][1] = r[2]; bhi[2 * jj + 1][1] = r[3];
            LDSM4(r, bBase + 2 * APLANE + jj * (16 * ROWB) + kk * 32);
            blo[2 * jj][0] = r[0]; blo[2 * jj + 1][0] = r[1];
            blo[2 * jj][1] = r[2]; blo[2 * jj + 1][1] = r[3];
        }
#pragma unroll
        for (int j = 0; j < 4; j++)
#pragma unroll
            for (int i = 0; i < 2; i++) {
                mma16816_f(A.f[i][j], ahi[i], bhi[j]);
                mma16816_h(A.h[i][j], ahi[i], blo[j]);
                mma16816_h(A.h[i][j], alo[i], bhi[j]);
            }
    }
}

__device__ __forceinline__ void epilogue_act(Acc& A, const float* __restrict__ bias,
                                             char* smem, int wm, int wn, int lane) {
    const int r4 = lane >> 2;
    uint32_t* stgH = (uint32_t*)(smem + SM_AHI);
    uint32_t* stgL = (uint32_t*)(smem + SM_ALO);
#pragma unroll
    for (int i = 0; i < 2; i++) {
        int r0 = wm + i * 16 + r4;
#pragma unroll
        for (int j = 0; j < 4; j++) {
            int c0 = wn + j * 8 + (lane & 3) * 2;
            float b0 = bias[c0], b1 = bias[c0 + 1];
            uint32_t hw, lw;
            split2(tanhf(A.f[i][j][0] + b0), tanhf(A.f[i][j][1] + b1), hw, lw);
            stgH[r0 * 68 + (c0 >> 1)] = hw;
            stgL[r0 * 68 + (c0 >> 1)] = lw;
            split2(tanhf(A.f[i][j][2] + b0), tanhf(A.f[i][j][3] + b1), hw, lw);
            stgH[(r0 + 8) * 68 + (c0 >> 1)] = hw;
            stgL[(r0 + 8) * 68 + (c0 >> 1)] = lw;
        }
    }
}

// L0(K=256) + L1 + L2 with tanh epilogues into the A region.
__device__ __forceinline__ void net3(char* smem, uint32_t sb, uint32_t aBase, uint32_t bBase,
                                     const float* __restrict__ bidsblk,
                                     const __half* w0, const __half* w1, const __half* w2,
                                     const float* b0, const float* b1, const float* b2,
                                     const __half* wpre_hi, const __half* wpre_lo,
                                     int wm, int wn, int lane, int tid, Acc& acc)
{
    acc.zero();
#pragma unroll 1
    for (int c = 0; c < 2; c++) {
        load_w(sb, w0, w0 + 32768, 0, c * 128, 256, tid);
        load_f32_pair(smem + SM_AHI, smem + SM_ALO,
                      (const float4*)(bidsblk + c * 128), 64, tid);
        CP_WAIT0(); __syncthreads();
        mma_phase(acc, aBase, bBase);
        __syncthreads();
    }
    load_w(sb, w1, w1 + 16384, 0, 0, 128, tid);
    acc.merge();
    epilogue_act(acc, b0, smem, wm, wn, lane);
    CP_WAIT0(); __syncthreads();

    acc.zero();
    mma_phase(acc, aBase, bBase);
    __syncthreads();
    load_w(sb, w2, w2 + 16384, 0, 0, 128, tid);
    acc.merge();
    epilogue_act(acc, b1, smem, wm, wn, lane);
    CP_WAIT0(); __syncthreads();

    acc.zero();
    mma_phase(acc, aBase, bBase);
    __syncthreads();
    if (wpre_hi) load_w(sb, wpre_hi, wpre_lo, 0, 0, 128, tid);
    acc.merge();
    epilogue_act(acc, b2, smem, wm, wn, lane);
    if (wpre_hi) CP_WAIT0();
    __syncthreads();
}

// ---------------- fused net kernel ---------------------------------------------
// grid (2, M/64): x = net (0 alloc, 1 pay), y = m-block. 256 threads, 2 CTA/SM.
__global__ void __launch_bounds__(256, 2)
fused_net(const float* __restrict__ bids, const __half* __restrict__ wt,
          const float* __restrict__ ab0, const float* __restrict__ ab1,
          const float* __restrict__ ab2, const float* __restrict__ ab3,
          const float* __restrict__ pb0, const float* __restrict__ pb1,
          const float* __restrict__ pb2,
          const float* __restrict__ pw3, const float* __restrict__ pb3,
          float* __restrict__ frac, float* __restrict__ psum,
          float* __restrict__ outA)
{
    extern __shared__ __align__(16) char smem[];
    const int tid  = threadIdx.x;
    const int lane = tid & 31;
    const int w    = tid >> 5;
    const int wm   = (w & 1) * 32;
    const int wn   = (w >> 1) * 32;
    const int bm   = blockIdx.y * 64;
    const bool pay = blockIdx.x != 0;

    const uint32_t sb = smem_u32(smem);
    const int l15 = lane & 15;
    const int lhi = (lane >> 4) * 16;
    const uint32_t aBase = sb + SM_AHI + (uint32_t)(wm + l15) * ROWB + lhi;
    const uint32_t bBase = sb + SM_BHI + (uint32_t)(wn + l15) * ROWB + lhi;
    const float* bidsblk = bids + (size_t)bm * 256;

    Acc acc;

    if (pay) {
        // ---------------- PAY NET + payment head -> frac ----------------
        net3(smem, sb, aBase, bBase, bidsblk,
             wt + OFF_PW0, wt + OFF_PW1, wt + OFF_PW2,
             pb0, pb1, pb2, nullptr, nullptr, wm, wn, lane, tid, acc);

        float* sW = (float*)(smem + SM_BHI);
#pragma unroll
        for (int t = 0; t < 8; t++) sW[t * 256 + tid] = pw3[t * 256 + tid];
        __syncthreads();
        const int s = tid >> 2, q = tid & 3;
        const __half* hh = (const __half*)(smem + SM_AHI) + s * 136;
        const __half* ll = (const __half*)(smem + SM_ALO) + s * 136;
        float a4[4];
#pragma unroll
        for (int j = 0; j < 4; j++) a4[j] = pb3[q * 4 + j];
#pragma unroll 8
        for (int k = 0; k < 128; k++) {
            float av = __half2float(hh[k]) + __half2float(ll[k]);
            const float* wr = sW + k * 16 + q * 4;
#pragma unroll
            for (int j = 0; j < 4; j++) a4[j] = fmaf(av, wr[j], a4[j]);
        }
        float* fo = frac + (size_t)(bm + s) * 16 + q * 4;
#pragma unroll
        for (int j = 0; j < 4; j++)
            fo[j] = __fdividef(1.f, 1.f + __expf(-a4[j]));
        return;
    }

    // ---------------- ALLOC NET ----------------
    net3(smem, sb, aBase, bBase, bidsblk,
         wt + OFF_AW0, wt + OFF_AW1, wt + OFF_AW2,
         ab0, ab1, ab2, wt + OFF_AW3, wt + OFF_AW3 + 32768,
         wm, wn, lane, tid, acc);

    // ---- L3: N=256 in two halves, staged to SMEM f32 (never global) ----
    acc.zero();
    mma_phase(acc, aBase, bBase);           // half0 (cols 0..127)
    __syncthreads();
    load_w(sb, wt + OFF_AW3, wt + OFF_AW3 + 32768, 128, 0, 128, tid);
    acc.merge();
    float m0[2][4][4];
#pragma unroll
    for (int i = 0; i < 2; i++)
#pragma unroll
        for (int j = 0; j < 4; j++)
#pragma unroll
            for (int z = 0; z < 4; z++) m0[i][j][z] = acc.f[i][j][z];
    CP_WAIT0(); __syncthreads();
    acc.zero();
    mma_phase(acc, aBase, bBase);           // half1 (cols 128..255)
    __syncthreads();
    acc.merge();

    {   // stage mat = raw + ab3, 64 x 256 f32 at row stride STG_ROW
        float* stage = (float*)smem;
        const int r4l = lane >> 2;
#pragma unroll
        for (int i = 0; i < 2; i++) {
            int r0 = wm + i * 16 + r4l;
#pragma unroll
            for (int j = 0; j < 4; j++) {
                int c0 = wn + j * 8 + (lane & 3) * 2;
                float b0 = ab3[c0], b1 = ab3[c0 + 1];
                float b2 = ab3[128 + c0], b3 = ab3[128 + c0 + 1];
                stage[r0 * STG_ROW + c0]             = m0[i][j][0] + b0;
                stage[r0 * STG_ROW + c0 + 1]         = m0[i][j][1] + b1;
                stage[(r0 + 8) * STG_ROW + c0]       = m0[i][j][2] + b0;
                stage[(r0 + 8) * STG_ROW + c0 + 1]   = m0[i][j][3] + b1;
                stage[r0 * STG_ROW + 128 + c0]           = acc.f[i][j][0] + b2;
                stage[r0 * STG_ROW + 128 + c0 + 1]       = acc.f[i][j][1] + b3;
                stage[(r0 + 8) * STG_ROW + 128 + c0]     = acc.f[i][j][2] + b2;
                stage[(r0 + 8) * STG_ROW + 128 + c0 + 1] = acc.f[i][j][3] + b3;
            }
        }
    }
    __syncthreads();

    // ---------------- SINKHORN (4 threads/sample) ----------------
    {
        const int s = tid >> 2, q = tid & 3;
        const float* srow = (const float*)smem + s * STG_ROW;
        float Kx[16][4];
#pragma unroll
        for (int i = 0; i < 16; i++) {
            float4 x = *(const float4*)(srow + i * 16 + q * 4);
            Kx[i][0] = __expf(x.x * 10.f);
            Kx[i][1] = __expf(x.y * 10.f);
            Kx[i][2] = __expf(x.z * 10.f);
            Kx[i][3] = __expf(x.w * 10.f);
        }
        float v[4] = {1.f, 1.f, 1.f, 1.f}, v16 = 1.f;
        float u[16], u16;

#pragma unroll 1
        for (int rnd = 0; rnd < 40; rnd++) {
            float r[17];
#pragma unroll
            for (int i = 0; i < 16; i++) {
                float a = Kx[i][0] * v[0];
                a = fmaf(Kx[i][1], v[1], a);
                a = fmaf(Kx[i][2], v[2], a);
                a = fmaf(Kx[i][3], v[3], a);
                r[i] = a;
            }
            r[16] = v[0] + v[1] + v[2] + v[3];
#pragma unroll
            for (int i = 0; i < 17; i++) {
                r[i] += __shfl_xor_sync(0xFFFFFFFFu, r[i], 1);
                r[i] += __shfl_xor_sync(0xFFFFFFFFu, r[i], 2);
            }
#pragma unroll
            for (int i = 0; i < 16; i++) u[i] = __fdividef(1.f, r[i] + v16);
            u16 = __fdividef(16.f, r[16] + v16);

            float usum = u[0];
#pragma unroll
            for (int i = 1; i < 16; i++) usum += u[i];
#pragma unroll
            for (int j = 0; j < 4; j++) {
                float c = u16;
#pragma unroll
                for (int i = 0; i < 16; i++) c = fmaf(Kx[i][j], u[i], c);
                v[j] = __fdividef(1.f, c);
            }
            v16 = __fdividef(16.f, usum + u16);
        }

        // outputs: allocs (own 4 cols) + unscaled row sums (psum)
        const float* brow = bids + (size_t)(bm + s) * 256;
        float* arow = outA + (size_t)(bm + s) * 256;
        float ps4[4];
#pragma unroll
        for (int i = 0; i < 16; i++) {
            float4 bb = *(const float4*)(brow + i * 16 + q * 4);
            float ui = u[i];
            float a0 = ui * Kx[i][0] * v[0], a1 = ui * Kx[i][1] * v[1];
            float a2 = ui * Kx[i][2] * v[2], a3 = ui * Kx[i][3] * v[3];
            *(float4*)(arow + i * 16 + q * 4) = make_float4(a0, a1, a2, a3);
            float pp = a0 * bb.x + a1 * bb.y + a2 * bb.z + a3 * bb.w;
            pp += __shfl_xor_sync(0xFFFFFFFFu, pp, 1);
            pp += __shfl_xor_sync(0xFFFFFFFFu, pp, 2);
            if ((i >> 2) == q) ps4[i & 3] = pp;
        }
        *(float4*)(psum + (size_t)(bm + s) * 16 + q * 4) =
            make_float4(ps4[0], ps4[1], ps4[2], ps4[3]);
    }
}

// ---------------- payments = frac * psum --------------------------------------
__global__ void pay_mul(const float* __restrict__ frac, const float* __restrict__ psum,
                        float* __restrict__ outP, int n)
{
    int t = blockIdx.x * 256 + threadIdx.x;
    if (t < n) outP[t] = frac[t] * psum[t];
}

// ---------------- launch -----------------------------------------------------
extern "C" void kernel_launch(void* const* d_in, const int* in_sizes, int n_in,
                              void* d_out, int out_size)
{
    const float* bids = (const float*)d_in[0];
    const float* aw0 = (const float*)d_in[1];  const float* ab0 = (const float*)d_in[2];
    const float* aw1 = (const float*)d_in[3];  const float* ab1 = (const float*)d_in[4];
    const float* aw2 = (const float*)d_in[5];  const float* ab2 = (const float*)d_in[6];
    const float* aw3 = (const float*)d_in[7];  const float* ab3 = (const float*)d_in[8];
    const float* pw0 = (const float*)d_in[9];  const float* pb0 = (const float*)d_in[10];
    const float* pw1 = (const float*)d_in[11]; const float* pb1 = (const float*)d_in[12];
    const float* pw2 = (const float*)d_in[13]; const float* pb2 = (const float*)d_in[14];
    const float* pw3 = (const float*)d_in[15]; const float* pb3 = (const float*)d_in[16];

    const int M = in_sizes[0] / 256;  // 32768

    void* p;
    cudaGetSymbolAddress(&p, g_wt);   __half* wt = (__half*)p;
    cudaGetSymbolAddress(&p, g_frac); float* fr  = (float*)p;
    cudaGetSymbolAddress(&p, g_psum); float* ps  = (float*)p;

    cudaFuncSetAttribute(fused_net, cudaFuncAttributeMaxDynamicSharedMemorySize,
                         SMEM_BYTES);

    pack_w_tile<<<dim3(32, 7), 256>>>(aw0, aw1, aw2, aw3, pw0, pw1, pw2, wt);

    float* out = (float*)d_out;
    fused_net<<<dim3(2, M / 64), 256, SMEM_BYTES>>>(
        bids, wt, ab0, ab1, ab2, ab3, pb0, pb1, pb2, pw3, pb3,
        fr, ps, out);

    pay_mul<<<(M * 16 + 255) / 256, 256>>>(fr, ps, out + (size_t)M * 256, M * 16);
}

// round 15
// speedup vs baseline: 1.1029x; 1.1029x over previous
#include <cuda_runtime.h>
#include <cuda_fp16.h>
#include <cstdint>
#include <math.h>

// DoubleNet (sm_103, HMMA): R12 topology (layer-fused MLP kernel per net +
// separate Sinkhorn) with a 4-thread/sample register-resident Sinkhorn
// (2 blocks/SM) and coalesced weight packing.
// B = 32768, D = 256, H = 128, A = I = 16, EPS = 0.1

#define MAXB 32768

__device__ float  g_mat [MAXB * 256];
__device__ float  g_frac[MAXB * 16];
__device__ __half g_wt[327680];   // per-weight: hi plane [N*K], lo plane [N*K]

// offsets in halves
#define OFF_AW0 0
#define OFF_AW1 65536
#define OFF_AW2 98304
#define OFF_AW3 131072
#define OFF_PW0 196608
#define OFF_PW1 262144
#define OFF_PW2 294912

// ---------------- helpers ----------------------------------------------------
__device__ __forceinline__ uint32_t smem_u32(const void* p) {
    uint32_t a;
    asm("{ .reg .u64 t; cvta.to.shared.u64 t, %1; cvt.u32.u64 %0, t; }"
        : "=r"(a) : "l"(p));
    return a;
}
__device__ __forceinline__ void split2(float x0, float x1, uint32_t& hw, uint32_t& lw) {
    __half h0 = __float2half_rn(x0), h1 = __float2half_rn(x1);
    __half l0 = __float2half_rn(x0 - __half2float(h0));
    __half l1 = __float2half_rn(x1 - __half2float(h1));
    hw = (uint32_t)__half_as_ushort(h0) | ((uint32_t)__half_as_ushort(h1) << 16);
    lw = (uint32_t)__half_as_ushort(l0) | ((uint32_t)__half_as_ushort(l1) << 16);
}
__device__ __forceinline__ void mma16816_f(float* d, const uint32_t* a, const uint32_t* b) {
    asm volatile(
        "mma.sync.aligned.m16n8k16.row.col.f32.f16.f16.f32 "
        "{%0,%1,%2,%3}, {%4,%5,%6,%7}, {%8,%9}, {%0,%1,%2,%3};"
        : "+f"(d[0]), "+f"(d[1]), "+f"(d[2]), "+f"(d[3])
        : "r"(a[0]), "r"(a[1]), "r"(a[2]), "r"(a[3]), "r"(b[0]), "r"(b[1]));
}
__device__ __forceinline__ void mma16816_h(uint32_t* d, const uint32_t* a, const uint32_t* b) {
    asm volatile(
        "mma.sync.aligned.m16n8k16.row.col.f16.f16.f16.f16 "
        "{%0,%1}, {%2,%3,%4,%5}, {%6,%7}, {%0,%1};"
        : "+r"(d[0]), "+r"(d[1])
        : "r"(a[0]), "r"(a[1]), "r"(a[2]), "r"(a[3]), "r"(b[0]), "r"(b[1]));
}
#define LDSM4(R, addr) \
    asm volatile("ldmatrix.sync.aligned.m8n8.x4.shared.b16 {%0,%1,%2,%3}, [%4];" \
                 : "=r"((R)[0]), "=r"((R)[1]), "=r"((R)[2]), "=r"((R)[3]) : "r"(addr))
#define CP_ASYNC16(dst, src) \
    asm volatile("cp.async.cg.shared.global [%0], [%1], 16;" :: "r"(dst), "l"(src))
#define CP_COMMIT() asm volatile("cp.async.commit_group;")
#define CP_WAIT0()  asm volatile("cp.async.wait_group 0;")

// ---------------- weight packing: SMEM tile transpose (coalesced both ways) ---
__global__ void pack_w_tile(const float* __restrict__ aw0, const float* __restrict__ aw1,
                            const float* __restrict__ aw2, const float* __restrict__ aw3,
                            const float* __restrict__ pw0, const float* __restrict__ pw1,
                            const float* __restrict__ pw2, __half* __restrict__ wt)
{
    const float* src; int K, N, off;
    switch (blockIdx.y) {
        case 0: src = aw0; K = 256; N = 128; off = OFF_AW0; break;
        case 1: src = aw1; K = 128; N = 128; off = OFF_AW1; break;
        case 2: src = aw2; K = 128; N = 128; off = OFF_AW2; break;
        case 3: src = aw3; K = 128; N = 256; off = OFF_AW3; break;
        case 4: src = pw0; K = 256; N = 128; off = OFF_PW0; break;
        case 5: src = pw1; K = 128; N = 128; off = OFF_PW1; break;
        default: src = pw2; K = 128; N = 128; off = OFF_PW2; break;
    }
    int tiles_n = N / 32;
    int tile = blockIdx.x;
    if (tile >= (K / 32) * tiles_n) return;
    int k0 = (tile / tiles_n) * 32, n0 = (tile % tiles_n) * 32;

    __shared__ float t[32][33];
    int c = threadIdx.x & 31, r8 = threadIdx.x >> 5;
#pragma unroll
    for (int j = 0; j < 4; j++) {
        int r = r8 + j * 8;
        t[r][c] = src[(size_t)(k0 + r) * N + n0 + c];
    }
    __syncthreads();
#pragma unroll
    for (int j = 0; j < 4; j++) {
        int n = r8 + j * 8;
        float v = t[c][n];
        __half h = __float2half_rn(v);
        size_t o = (size_t)(n0 + n) * K + k0 + c;
        wt[off + o]                 = h;
        wt[off + (size_t)N * K + o] = __float2half_rn(v - __half2float(h));
    }
}

// ---------------- SMEM layout ------------------------------------------------
#define ROWB   272
#define APLANE 17408
#define SM_AHI 0
#define SM_ALO 17408
#define SM_BHI 34816
#define SM_BLO 69632
#define SMEM_BYTES 104448

__device__ __forceinline__ void cpa128(uint32_t dst, const __half* __restrict__ src,
                                       int stride_h, int tid) {
#pragma unroll
    for (int j = 0; j < 8; j++) {
        int lin = j * 256 + tid;
        int row = lin >> 4;
        int q   = lin & 15;
        CP_ASYNC16(dst + row * ROWB + q * 16, src + row * stride_h + q * 8);
    }
}
__device__ __forceinline__ void load_w(uint32_t sb, const __half* __restrict__ whi,
                                       const __half* __restrict__ wlo,
                                       int noff, int koff, int K, int tid) {
    cpa128(sb + SM_BHI, whi + (size_t)noff * K + koff, K, tid);
    cpa128(sb + SM_BLO, wlo + (size_t)noff * K + koff, K, tid);
    CP_COMMIT();
}
__device__ __forceinline__ void load_f32_pair(char* hi, char* lo,
                                              const float4* __restrict__ src,
                                              int stride16, int tid) {
#pragma unroll
    for (int j = 0; j < 8; j++) {
        int lin = j * 256 + tid;
        int row = lin >> 5;
        int g   = lin & 31;
        float4 v = src[row * stride16 + g];
        uint32_t h0, l0, h1, l1;
        split2(v.x, v.y, h0, l0);
        split2(v.z, v.w, h1, l1);
        int off = row * ROWB + g * 8;
        *(uint2*)(hi + off) = make_uint2(h0, h1);
        *(uint2*)(lo + off) = make_uint2(l0, l1);
    }
}

// ---------------- MMA tile ----------------------------------------------------
struct Acc {
    float    f[2][4][4];
    uint32_t h[2][4][2];
    __device__ __forceinline__ void zero() {
#pragma unroll
        for (int i = 0; i < 2; i++)
#pragma unroll
            for (int j = 0; j < 4; j++) {
#pragma unroll
                for (int q = 0; q < 4; q++) f[i][j][q] = 0.f;
                h[i][j][0] = 0u; h[i][j][1] = 0u;
            }
    }
    __device__ __forceinline__ void merge() {
#pragma unroll
        for (int i = 0; i < 2; i++)
#pragma unroll
            for (int j = 0; j < 4; j++) {
                float2 f0 = __half22float2(*reinterpret_cast<__half2*>(&h[i][j][0]));
                float2 f1 = __half22float2(*reinterpret_cast<__half2*>(&h[i][j][1]));
                f[i][j][0] += f0.x; f[i][j][1] += f0.y;
                f[i][j][2] += f1.x; f[i][j][3] += f1.y;
            }
    }
};

__device__ __forceinline__ void mma_phase(Acc& A, uint32_t aBase, uint32_t bBase) {
#pragma unroll
    for (int kk = 0; kk < 8; kk++) {
        uint32_t ahi[2][4], alo[2][4];
#pragma unroll
        for (int i = 0; i < 2; i++) {
            LDSM4(ahi[i], aBase + i * (16 * ROWB) + kk * 32);
            LDSM4(alo[i], aBase + APLANE + i * (16 * ROWB) + kk * 32);
        }
        uint32_t bhi[4][2], blo[4][2];
#pragma unroll
        for (int jj = 0; jj < 2; jj++) {
            uint32_t r[4];
            LDSM4(r, bBase + jj * (16 * ROWB) + kk * 32);
            bhi[2 * jj][0] = r[0]; bhi[2 * jj + 1][0] = r[1];
            bhi[2 * jj][1] = r[2]; bhi[2 * jj + 1][1] = r[3];
            LDSM4(r, bBase + 2 * APLANE + jj * (16 * ROWB) + kk * 32);
            blo[2 * jj][0] = r[0]; blo[2 * jj + 1][0] = r[1];
            blo[2 * jj][1] = r[2]; blo[2 * jj + 1][1] = r[3];
        }
#pragma unroll
        for (int j = 0; j < 4; j++)
#pragma unroll
            for (int i = 0; i < 2; i++) {
                mma16816_f(A.f[i][j], ahi[i], bhi[j]);
                mma16816_h(A.h[i][j], ahi[i], blo[j]);
                mma16816_h(A.h[i][j], alo[i], bhi[j]);
            }
    }
}

__device__ __forceinline__ void epilogue_act(Acc& A, const float* __restrict__ bias,
                                             char* smem, int wm, int wn, int lane) {
    const int r4 = lane >> 2;
    uint32_t* stgH = (uint32_t*)(smem + SM_AHI);
    uint32_t* stgL = (uint32_t*)(smem + SM_ALO);
#pragma unroll
    for (int i = 0; i < 2; i++) {
        int r0 = wm + i * 16 + r4;
#pragma unroll
        for (int j = 0; j < 4; j++) {
            int c0 = wn + j * 8 + (lane & 3) * 2;
            float b0 = bias[c0], b1 = bias[c0 + 1];
            uint32_t hw, lw;
            split2(tanhf(A.f[i][j][0] + b0), tanhf(A.f[i][j][1] + b1), hw, lw);
            stgH[r0 * 68 + (c0 >> 1)] = hw;
            stgL[r0 * 68 + (c0 >> 1)] = lw;
            split2(tanhf(A.f[i][j][2] + b0), tanhf(A.f[i][j][3] + b1), hw, lw);
            stgH[(r0 + 8) * 68 + (c0 >> 1)] = hw;
            stgL[(r0 + 8) * 68 + (c0 >> 1)] = lw;
        }
    }
}

// ---------------- fused 4-layer MLP (R12, unchanged) --------------------------
// grid (M/64, 2): x = m-block, y = net (0 alloc, 1 pay). 256 threads, 2 CTA/SM.
__global__ void __launch_bounds__(256, 2)
fused_mlp(const float* __restrict__ bids, const __half* __restrict__ wt,
          const float* __restrict__ ab0, const float* __restrict__ ab1,
          const float* __restrict__ ab2, const float* __restrict__ ab3,
          const float* __restrict__ pb0, const float* __restrict__ pb1,
          const float* __restrict__ pb2,
          const float* __restrict__ pw3, const float* __restrict__ pb3,
          float* __restrict__ mat, float* __restrict__ frac)
{
    extern __shared__ __align__(16) char smem[];
    const int tid  = threadIdx.x;
    const int lane = tid & 31;
    const int w    = tid >> 5;
    const int wm   = (w & 1) * 32;
    const int wn   = (w >> 1) * 32;
    const int bm   = blockIdx.x * 64;
    const bool pay = blockIdx.y != 0;

    const uint32_t sb = smem_u32(smem);
    const int l15 = lane & 15;
    const int lhi = (lane >> 4) * 16;
    const uint32_t aBase = sb + SM_AHI + (uint32_t)(wm + l15) * ROWB + lhi;
    const uint32_t bBase = sb + SM_BHI + (uint32_t)(wn + l15) * ROWB + lhi;

    const __half* w0h = wt + (pay ? OFF_PW0 : OFF_AW0);
    const __half* w1h = wt + (pay ? OFF_PW1 : OFF_AW1);
    const __half* w2h = wt + (pay ? OFF_PW2 : OFF_AW2);
    const float* b0 = pay ? pb0 : ab0;
    const float* b1 = pay ? pb1 : ab1;
    const float* b2 = pay ? pb2 : ab2;

    Acc acc;

    // ---- L0: K=256 (2 chunks), A from bids f32
    acc.zero();
#pragma unroll 1
    for (int c = 0; c < 2; c++) {
        load_w(sb, w0h, w0h + 32768, 0, c * 128, 256, tid);
        load_f32_pair(smem + SM_AHI, smem + SM_ALO,
                      (const float4*)(bids + (size_t)bm * 256 + c * 128), 64, tid);
        CP_WAIT0(); __syncthreads();
        mma_phase(acc, aBase, bBase);
        __syncthreads();
    }
    load_w(sb, w1h, w1h + 16384, 0, 0, 128, tid);   // prefetch L1 W over epilogue
    acc.merge();
    epilogue_act(acc, b0, smem, wm, wn, lane);
    CP_WAIT0(); __syncthreads();

    // ---- L1
    acc.zero();
    mma_phase(acc, aBase, bBase);
    __syncthreads();
    load_w(sb, w2h, w2h + 16384, 0, 0, 128, tid);   // prefetch L2 W
    acc.merge();
    epilogue_act(acc, b1, smem, wm, wn, lane);
    CP_WAIT0(); __syncthreads();

    // ---- L2
    acc.zero();
    mma_phase(acc, aBase, bBase);
    __syncthreads();
    if (!pay)
        load_w(sb, wt + OFF_AW3, wt + OFF_AW3 + 32768, 0, 0, 128, tid);  // L3 half0
    acc.merge();
    epilogue_act(acc, b2, smem, wm, wn, lane);
    CP_WAIT0(); __syncthreads();

    if (!pay) {
        // ---- L3: N=256 in two halves, f32 -> mat
#pragma unroll 1
        for (int h = 0; h < 2; h++) {
            acc.zero();
            mma_phase(acc, aBase, bBase);
            __syncthreads();
            acc.merge();
            float* stage = (float*)(smem + SM_BHI);   // W consumed; 64x132 f32
            const int r4 = lane >> 2;
#pragma unroll
            for (int i = 0; i < 2; i++) {
                int r0 = wm + i * 16 + r4;
#pragma unroll
                for (int j = 0; j < 4; j++) {
                    int c0 = wn + j * 8 + (lane & 3) * 2;
                    float bb0 = ab3[h * 128 + c0], bb1 = ab3[h * 128 + c0 + 1];
                    stage[r0 * 132 + c0]           = acc.f[i][j][0] + bb0;
                    stage[r0 * 132 + c0 + 1]       = acc.f[i][j][1] + bb1;
                    stage[(r0 + 8) * 132 + c0]     = acc.f[i][j][2] + bb0;
                    stage[(r0 + 8) * 132 + c0 + 1] = acc.f[i][j][3] + bb1;
                }
            }
            __syncthreads();
            float* og = mat + (size_t)bm * 256 + h * 128;
#pragma unroll
            for (int it = 0; it < 32; it++) {
                int lin = it * 256 + tid;
                int row = lin >> 7, col = lin & 127;
                og[row * 256 + col] = stage[row * 132 + col];
            }
            if (h == 0) {
                __syncthreads();   // stage fully read before W overwrite
                load_w(sb, wt + OFF_AW3, wt + OFF_AW3 + 32768, 128, 0, 128, tid);
                CP_WAIT0(); __syncthreads();
            }
        }
    } else {
        // ---- payment head: frac = sigmoid(acts @ pw3 + pb3)
        float* sW = (float*)(smem + SM_BHI);
#pragma unroll
        for (int t = 0; t < 8; t++) sW[t * 256 + tid] = pw3[t * 256 + tid];
        __syncthreads();
        const int s = tid >> 2, q = tid & 3;
        const __half* hh = (const __half*)(smem + SM_AHI) + s * 136;
        const __half* ll = (const __half*)(smem + SM_ALO) + s * 136;
        float a4[4];
#pragma unroll
        for (int j = 0; j < 4; j++) a4[j] = pb3[q * 4 + j];
#pragma unroll 8
        for (int k = 0; k < 128; k++) {
            float av = __half2float(hh[k]) + __half2float(ll[k]);
            const float* wr = sW + k * 16 + q * 4;
#pragma unroll
            for (int j = 0; j < 4; j++) a4[j] = fmaf(av, wr[j], a4[j]);
        }
        float* fo = frac + (size_t)(bm + s) * 16 + q * 4;
#pragma unroll
        for (int j = 0; j < 4; j++)
            fo[j] = __fdividef(1.f, 1.f + __expf(-a4[j]));
    }
}

// ---------------- Sinkhorn: 4 threads/sample, 2 blocks/SM ---------------------
// Thread q of sample s owns columns [4q, 4q+4): K[16][4] in registers (~64).
// Row pass: local partials + 2-level shfl.bfly; col pass fully local.
__global__ void __launch_bounds__(256, 2) sinkhorn4(
    const float* __restrict__ mat, const float* __restrict__ bids,
    const float* __restrict__ frac, float* __restrict__ outA,
    float* __restrict__ outP)
{
    const int tid = threadIdx.x;
    const int q   = tid & 3;
    const int s   = blockIdx.x * 64 + (tid >> 2);
    const float* srow = mat + (size_t)s * 256;

    float Kx[16][4];
#pragma unroll
    for (int i = 0; i < 16; i++) {
        float4 x = *(const float4*)(srow + i * 16 + q * 4);
        Kx[i][0] = __expf(x.x * 10.f);
        Kx[i][1] = __expf(x.y * 10.f);
        Kx[i][2] = __expf(x.z * 10.f);
        Kx[i][3] = __expf(x.w * 10.f);
    }
    float v[4] = {1.f, 1.f, 1.f, 1.f}, v16 = 1.f;
    float u[16], u16;

#pragma unroll 1
    for (int rnd = 0; rnd < 40; rnd++) {
        float r[17];
#pragma unroll
        for (int i = 0; i < 16; i++) {
            float a = Kx[i][0] * v[0];
            a = fmaf(Kx[i][1], v[1], a);
            a = fmaf(Kx[i][2], v[2], a);
            a = fmaf(Kx[i][3], v[3], a);
            r[i] = a;
        }
        r[16] = v[0] + v[1] + v[2] + v[3];
#pragma unroll
        for (int i = 0; i < 17; i++) {
            r[i] += __shfl_xor_sync(0xFFFFFFFFu, r[i], 1);
            r[i] += __shfl_xor_sync(0xFFFFFFFFu, r[i], 2);
        }
#pragma unroll
        for (int i = 0; i < 16; i++) u[i] = __fdividef(1.f, r[i] + v16);
        u16 = __fdividef(16.f, r[16] + v16);

        float usum = u[0];
#pragma unroll
        for (int i = 1; i < 16; i++) usum += u[i];
#pragma unroll
        for (int j = 0; j < 4; j++) {
            float c = u16;
#pragma unroll
            for (int i = 0; i < 16; i++) c = fmaf(Kx[i][j], u[i], c);
            v[j] = __fdividef(1.f, c);
        }
        v16 = __fdividef(16.f, usum + u16);
    }

    // outputs: allocs (own 4 cols) + payments (frac scale on owned rows)
    const float* brow = bids + (size_t)s * 256;
    float* arow = outA + (size_t)s * 256;
    float pay4[4];
#pragma unroll
    for (int i = 0; i < 16; i++) {
        float4 bb = *(const float4*)(brow + i * 16 + q * 4);
        float ui = u[i];
        float a0 = ui * Kx[i][0] * v[0], a1 = ui * Kx[i][1] * v[1];
        float a2 = ui * Kx[i][2] * v[2], a3 = ui * Kx[i][3] * v[3];
        *(float4*)(arow + i * 16 + q * 4) = make_float4(a0, a1, a2, a3);
        float pp = a0 * bb.x + a1 * bb.y + a2 * bb.z + a3 * bb.w;
        pp += __shfl_xor_sync(0xFFFFFFFFu, pp, 1);
        pp += __shfl_xor_sync(0xFFFFFFFFu, pp, 2);
        if ((i >> 2) == q) pay4[i & 3] = pp;
    }
    float4 fv = *(const float4*)(frac + (size_t)s * 16 + q * 4);
    *(float4*)(outP + (size_t)s * 16 + q * 4) =
        make_float4(pay4[0] * fv.x, pay4[1] * fv.y, pay4[2] * fv.z, pay4[3] * fv.w);
}

// ---------------- launch -----------------------------------------------------
extern "C" void kernel_launch(void* const* d_in, const int* in_sizes, int n_in,
                              void* d_out, int out_size)
{
    const float* bids = (const float*)d_in[0];
    const float* aw0 = (const float*)d_in[1];  const float* ab0 = (const float*)d_in[2];
    const float* aw1 = (const float*)d_in[3];  const float* ab1 = (const float*)d_in[4];
    const float* aw2 = (const float*)d_in[5];  const float* ab2 = (const float*)d_in[6];
    const float* aw3 = (const float*)d_in[7];  const float* ab3 = (const float*)d_in[8];
    const float* pw0 = (const float*)d_in[9];  const float* pb0 = (const float*)d_in[10];
    const float* pw1 = (const float*)d_in[11]; const float* pb1 = (const float*)d_in[12];
    const float* pw2 = (const float*)d_in[13]; const float* pb2 = (const float*)d_in[14];
    const float* pw3 = (const float*)d_in[15]; const float* pb3 = (const float*)d_in[16];

    const int M = in_sizes[0] / 256;  // 32768

    void* p;
    cudaGetSymbolAddress(&p, g_mat);  float* mat = (float*)p;
    cudaGetSymbolAddress(&p, g_frac); float* fr  = (float*)p;
    cudaGetSymbolAddress(&p, g_wt);   __half* wt = (__half*)p;

    cudaFuncSetAttribute(fused_mlp, cudaFuncAttributeMaxDynamicSharedMemorySize,
                         SMEM_BYTES);

    pack_w_tile<<<dim3(32, 7), 256>>>(aw0, aw1, aw2, aw3, pw0, pw1, pw2, wt);

    fused_mlp<<<dim3(M / 64, 2), 256, SMEM_BYTES>>>(
        bids, wt, ab0, ab1, ab2, ab3, pb0, pb1, pb2, pw3, pb3, mat, fr);

    float* out = (float*)d_out;
    sinkhorn4<<<M / 64, 256>>>(mat, bids, fr, out, out + (size_t)M * 256);
}

// round 16
// speedup vs baseline: 1.1451x; 1.0383x over previous
#include <cuda_runtime.h>
#include <cuda_fp16.h>
#include <cstdint>
#include <math.h>

// DoubleNet (sm_103, HMMA): R12 topology (layer-fused MLP kernel per net +
// separate 2-thr/sample Sinkhorn), MUFU-based fast tanh in epilogues,
// coalesced weight packing.
// B = 32768, D = 256, H = 128, A = I = 16, EPS = 0.1

#define MAXB 32768

__device__ float  g_mat [MAXB * 256];
__device__ float  g_frac[MAXB * 16];
__device__ __half g_wt[327680];   // per-weight: hi plane [N*K], lo plane [N*K]

// offsets in halves
#define OFF_AW0 0
#define OFF_AW1 65536
#define OFF_AW2 98304
#define OFF_AW3 131072
#define OFF_PW0 196608
#define OFF_PW1 262144
#define OFF_PW2 294912

// ---------------- helpers ----------------------------------------------------
__device__ __forceinline__ uint32_t smem_u32(const void* p) {
    uint32_t a;
    asm("{ .reg .u64 t; cvta.to.shared.u64 t, %1; cvt.u32.u64 %0, t; }"
        : "=r"(a) : "l"(p));
    return a;
}
// fast tanh via MUFU ex2/rcp: t = 1 - 2/(e^{2x}+1).  |rel err| ~1e-6.
// Saturation exact: exp->inf => 1, exp->0 => -1.
__device__ __forceinline__ float ftanh(float x) {
    float e = __expf(2.f * x);
    return 1.f - __fdividef(2.f, e + 1.f);
}
__device__ __forceinline__ void split2(float x0, float x1, uint32_t& hw, uint32_t& lw) {
    __half h0 = __float2half_rn(x0), h1 = __float2half_rn(x1);
    __half l0 = __float2half_rn(x0 - __half2float(h0));
    __half l1 = __float2half_rn(x1 - __half2float(h1));
    hw = (uint32_t)__half_as_ushort(h0) | ((uint32_t)__half_as_ushort(h1) << 16);
    lw = (uint32_t)__half_as_ushort(l0) | ((uint32_t)__half_as_ushort(l1) << 16);
}
__device__ __forceinline__ void mma16816_f(float* d, const uint32_t* a, const uint32_t* b) {
    asm volatile(
        "mma.sync.aligned.m16n8k16.row.col.f32.f16.f16.f32 "
        "{%0,%1,%2,%3}, {%4,%5,%6,%7}, {%8,%9}, {%0,%1,%2,%3};"
        : "+f"(d[0]), "+f"(d[1]), "+f"(d[2]), "+f"(d[3])
        : "r"(a[0]), "r"(a[1]), "r"(a[2]), "r"(a[3]), "r"(b[0]), "r"(b[1]));
}
__device__ __forceinline__ void mma16816_h(uint32_t* d, const uint32_t* a, const uint32_t* b) {
    asm volatile(
        "mma.sync.aligned.m16n8k16.row.col.f16.f16.f16.f16 "
        "{%0,%1}, {%2,%3,%4,%5}, {%6,%7}, {%0,%1};"
        : "+r"(d[0]), "+r"(d[1])
        : "r"(a[0]), "r"(a[1]), "r"(a[2]), "r"(a[3]), "r"(b[0]), "r"(b[1]));
}
#define LDSM4(R, addr) \
    asm volatile("ldmatrix.sync.aligned.m8n8.x4.shared.b16 {%0,%1,%2,%3}, [%4];" \
                 : "=r"((R)[0]), "=r"((R)[1]), "=r"((R)[2]), "=r"((R)[3]) : "r"(addr))
#define CP_ASYNC16(dst, src) \
    asm volatile("cp.async.cg.shared.global [%0], [%1], 16;" :: "r"(dst), "l"(src))
#define CP_COMMIT() asm volatile("cp.async.commit_group;")
#define CP_WAIT0()  asm volatile("cp.async.wait_group 0;")

// ---------------- weight packing: SMEM tile transpose -------------------------
__global__ void pack_w_tile(const float* __restrict__ aw0, const float* __restrict__ aw1,
                            const float* __restrict__ aw2, const float* __restrict__ aw3,
                            const float* __restrict__ pw0, const float* __restrict__ pw1,
                            const float* __restrict__ pw2, __half* __restrict__ wt)
{
    const float* src; int K, N, off;
    switch (blockIdx.y) {
        case 0: src = aw0; K = 256; N = 128; off = OFF_AW0; break;
        case 1: src = aw1; K = 128; N = 128; off = OFF_AW1; break;
        case 2: src = aw2; K = 128; N = 128; off = OFF_AW2; break;
        case 3: src = aw3; K = 128; N = 256; off = OFF_AW3; break;
        case 4: src = pw0; K = 256; N = 128; off = OFF_PW0; break;
        case 5: src = pw1; K = 128; N = 128; off = OFF_PW1; break;
        default: src = pw2; K = 128; N = 128; off = OFF_PW2; break;
    }
    int tiles_n = N / 32;
    int tile = blockIdx.x;
    if (tile >= (K / 32) * tiles_n) return;
    int k0 = (tile / tiles_n) * 32, n0 = (tile % tiles_n) * 32;

    __shared__ float t[32][33];
    int c = threadIdx.x & 31, r8 = threadIdx.x >> 5;
#pragma unroll
    for (int j = 0; j < 4; j++) {
        int r = r8 + j * 8;
        t[r][c] = src[(size_t)(k0 + r) * N + n0 + c];
    }
    __syncthreads();
#pragma unroll
    for (int j = 0; j < 4; j++) {
        int n = r8 + j * 8;
        float v = t[c][n];
        __half h = __float2half_rn(v);
        size_t o = (size_t)(n0 + n) * K + k0 + c;
        wt[off + o]                 = h;
        wt[off + (size_t)N * K + o] = __float2half_rn(v - __half2float(h));
    }
}

// ---------------- SMEM layout ------------------------------------------------
#define ROWB   272
#define APLANE 17408
#define SM_AHI 0
#define SM_ALO 17408
#define SM_BHI 34816
#define SM_BLO 69632
#define SMEM_BYTES 104448

__device__ __forceinline__ void cpa128(uint32_t dst, const __half* __restrict__ src,
                                       int stride_h, int tid) {
#pragma unroll
    for (int j = 0; j < 8; j++) {
        int lin = j * 256 + tid;
        int row = lin >> 4;
        int q   = lin & 15;
        CP_ASYNC16(dst + row * ROWB + q * 16, src + row * stride_h + q * 8);
    }
}
__device__ __forceinline__ void load_w(uint32_t sb, const __half* __restrict__ whi,
                                       const __half* __restrict__ wlo,
                                       int noff, int koff, int K, int tid) {
    cpa128(sb + SM_BHI, whi + (size_t)noff * K + koff, K, tid);
    cpa128(sb + SM_BLO, wlo + (size_t)noff * K + koff, K, tid);
    CP_COMMIT();
}
__device__ __forceinline__ void load_f32_pair(char* hi, char* lo,
                                              const float4* __restrict__ src,
                                              int stride16, int tid) {
#pragma unroll
    for (int j = 0; j < 8; j++) {
        int lin = j * 256 + tid;
        int row = lin >> 5;
        int g   = lin & 31;
        float4 v = src[row * stride16 + g];
        uint32_t h0, l0, h1, l1;
        split2(v.x, v.y, h0, l0);
        split2(v.z, v.w, h1, l1);
        int off = row * ROWB + g * 8;
        *(uint2*)(hi + off) = make_uint2(h0, h1);
        *(uint2*)(lo + off) = make_uint2(l0, l1);
    }
}

// ---------------- MMA tile ----------------------------------------------------
struct Acc {
    float    f[2][4][4];
    uint32_t h[2][4][2];
    __device__ __forceinline__ void zero() {
#pragma unroll
        for (int i = 0; i < 2; i++)
#pragma unroll
            for (int j = 0; j < 4; j++) {
#pragma unroll
                for (int q = 0; q < 4; q++) f[i][j][q] = 0.f;
                h[i][j][0] = 0u; h[i][j][1] = 0u;
            }
    }
    __device__ __forceinline__ void merge() {
#pragma unroll
        for (int i = 0; i < 2; i++)
#pragma unroll
            for (int j = 0; j < 4; j++) {
                float2 f0 = __half22float2(*reinterpret_cast<__half2*>(&h[i][j][0]));
                float2 f1 = __half22float2(*reinterpret_cast<__half2*>(&h[i][j][1]));
                f[i][j][0] += f0.x; f[i][j][1] += f0.y;
                f[i][j][2] += f1.x; f[i][j][3] += f1.y;
            }
    }
};

__device__ __forceinline__ void mma_phase(Acc& A, uint32_t aBase, uint32_t bBase) {
#pragma unroll
    for (int kk = 0; kk < 8; kk++) {
        uint32_t ahi[2][4], alo[2][4];
#pragma unroll
        for (int i = 0; i < 2; i++) {
            LDSM4(ahi[i], aBase + i * (16 * ROWB) + kk * 32);
            LDSM4(alo[i], aBase + APLANE + i * (16 * ROWB) + kk * 32);
        }
        uint32_t bhi[4][2], blo[4][2];
#pragma unroll
        for (int jj = 0; jj < 2; jj++) {
            uint32_t r[4];
            LDSM4(r, bBase + jj * (16 * ROWB) + kk * 32);
            bhi[2 * jj][0] = r[0]; bhi[2 * jj + 1][0] = r[1];
            bhi[2 * jj][1] = r[2]; bhi[2 * jj + 1][1] = r[3];
            LDSM4(r, bBase + 2 * APLANE + jj * (16 * ROWB) + kk * 32);
            blo[2 * jj][0] = r[0]; blo[2 * jj + 1][0] = r[1];
            blo[2 * jj][1] = r[2]; blo[2 * jj + 1][1] = r[3];
        }
#pragma unroll
        for (int j = 0; j < 4; j++)
#pragma unroll
            for (int i = 0; i < 2; i++) {
                mma16816_f(A.f[i][j], ahi[i], bhi[j]);
                mma16816_h(A.h[i][j], ahi[i], blo[j]);
                mma16816_h(A.h[i][j], alo[i], bhi[j]);
            }
    }
}

__device__ __forceinline__ void epilogue_act(Acc& A, const float* __restrict__ bias,
                                             char* smem, int wm, int wn, int lane) {
    const int r4 = lane >> 2;
    uint32_t* stgH = (uint32_t*)(smem + SM_AHI);
    uint32_t* stgL = (uint32_t*)(smem + SM_ALO);
#pragma unroll
    for (int i = 0; i < 2; i++) {
        int r0 = wm + i * 16 + r4;
#pragma unroll
        for (int j = 0; j < 4; j++) {
            int c0 = wn + j * 8 + (lane & 3) * 2;
            float b0 = bias[c0], b1 = bias[c0 + 1];
            uint32_t hw, lw;
            split2(ftanh(A.f[i][j][0] + b0), ftanh(A.f[i][j][1] + b1), hw, lw);
            stgH[r0 * 68 + (c0 >> 1)] = hw;
            stgL[r0 * 68 + (c0 >> 1)] = lw;
            split2(ftanh(A.f[i][j][2] + b0), ftanh(A.f[i][j][3] + b1), hw, lw);
            stgH[(r0 + 8) * 68 + (c0 >> 1)] = hw;
            stgL[(r0 + 8) * 68 + (c0 >> 1)] = lw;
        }
    }
}

// ---------------- fused 4-layer MLP (R12 structure) ---------------------------
// grid (M/64, 2): x = m-block, y = net (0 alloc, 1 pay). 256 threads, 2 CTA/SM.
__global__ void __launch_bounds__(256, 2)
fused_mlp(const float* __restrict__ bids, const __half* __restrict__ wt,
          const float* __restrict__ ab0, const float* __restrict__ ab1,
          const float* __restrict__ ab2, const float* __restrict__ ab3,
          const float* __restrict__ pb0, const float* __restrict__ pb1,
          const float* __restrict__ pb2,
          const float* __restrict__ pw3, const float* __restrict__ pb3,
          float* __restrict__ mat, float* __restrict__ frac)
{
    extern __shared__ __align__(16) char smem[];
    const int tid  = threadIdx.x;
    const int lane = tid & 31;
    const int w    = tid >> 5;
    const int wm   = (w & 1) * 32;
    const int wn   = (w >> 1) * 32;
    const int bm   = blockIdx.x * 64;
    const bool pay = blockIdx.y != 0;

    const uint32_t sb = smem_u32(smem);
    const int l15 = lane & 15;
    const int lhi = (lane >> 4) * 16;
    const uint32_t aBase = sb + SM_AHI + (uint32_t)(wm + l15) * ROWB + lhi;
    const uint32_t bBase = sb + SM_BHI + (uint32_t)(wn + l15) * ROWB + lhi;

    const __half* w0h = wt + (pay ? OFF_PW0 : OFF_AW0);
    const __half* w1h = wt + (pay ? OFF_PW1 : OFF_AW1);
    const __half* w2h = wt + (pay ? OFF_PW2 : OFF_AW2);
    const float* b0 = pay ? pb0 : ab0;
    const float* b1 = pay ? pb1 : ab1;
    const float* b2 = pay ? pb2 : ab2;

    Acc acc;

    // ---- L0: K=256 (2 chunks), A from bids f32
    acc.zero();
#pragma unroll 1
    for (int c = 0; c < 2; c++) {
        load_w(sb, w0h, w0h + 32768, 0, c * 128, 256, tid);
        load_f32_pair(smem + SM_AHI, smem + SM_ALO,
                      (const float4*)(bids + (size_t)bm * 256 + c * 128), 64, tid);
        CP_WAIT0(); __syncthreads();
        mma_phase(acc, aBase, bBase);
        __syncthreads();
    }
    load_w(sb, w1h, w1h + 16384, 0, 0, 128, tid);   // prefetch L1 W over epilogue
    acc.merge();
    epilogue_act(acc, b0, smem, wm, wn, lane);
    CP_WAIT0(); __syncthreads();

    // ---- L1
    acc.zero();
    mma_phase(acc, aBase, bBase);
    __syncthreads();
    load_w(sb, w2h, w2h + 16384, 0, 0, 128, tid);   // prefetch L2 W
    acc.merge();
    epilogue_act(acc, b1, smem, wm, wn, lane);
    CP_WAIT0(); __syncthreads();

    // ---- L2
    acc.zero();
    mma_phase(acc, aBase, bBase);
    __syncthreads();
    if (!pay)
        load_w(sb, wt + OFF_AW3, wt + OFF_AW3 + 32768, 0, 0, 128, tid);  // L3 half0
    acc.merge();
    epilogue_act(acc, b2, smem, wm, wn, lane);
    CP_WAIT0(); __syncthreads();

    if (!pay) {
        // ---- L3: N=256 in two halves, f32 -> mat
#pragma unroll 1
        for (int h = 0; h < 2; h++) {
            acc.zero();
            mma_phase(acc, aBase, bBase);
            __syncthreads();
            acc.merge();
            float* stage = (float*)(smem + SM_BHI);   // W consumed; 64x132 f32
            const int r4 = lane >> 2;
#pragma unroll
            for (int i = 0; i < 2; i++) {
                int r0 = wm + i * 16 + r4;
#pragma unroll
                for (int j = 0; j < 4; j++) {
                    int c0 = wn + j * 8 + (lane & 3) * 2;
                    float bb0 = ab3[h * 128 + c0], bb1 = ab3[h * 128 + c0 + 1];
                    stage[r0 * 132 + c0]           = acc.f[i][j][0] + bb0;
                    stage[r0 * 132 + c0 + 1]       = acc.f[i][j][1] + bb1;
                    stage[(r0 + 8) * 132 + c0]     = acc.f[i][j][2] + bb0;
                    stage[(r0 + 8) * 132 + c0 + 1] = acc.f[i][j][3] + bb1;
                }
            }
            __syncthreads();
            float* og = mat + (size_t)bm * 256 + h * 128;
#pragma unroll
            for (int it = 0; it < 32; it++) {
                int lin = it * 256 + tid;
                int row = lin >> 7, col = lin & 127;
                og[row * 256 + col] = stage[row * 132 + col];
            }
            if (h == 0) {
                __syncthreads();   // stage fully read before W overwrite
                load_w(sb, wt + OFF_AW3, wt + OFF_AW3 + 32768, 128, 0, 128, tid);
                CP_WAIT0(); __syncthreads();
            }
        }
    } else {
        // ---- payment head: frac = sigmoid(acts @ pw3 + pb3)
        float* sW = (float*)(smem + SM_BHI);
#pragma unroll
        for (int t = 0; t < 8; t++) sW[t * 256 + tid] = pw3[t * 256 + tid];
        __syncthreads();
        const int s = tid >> 2, q = tid & 3;
        const __half* hh = (const __half*)(smem + SM_AHI) + s * 136;
        const __half* ll = (const __half*)(smem + SM_ALO) + s * 136;
        float a4[4];
#pragma unroll
        for (int j = 0; j < 4; j++) a4[j] = pb3[q * 4 + j];
#pragma unroll 8
        for (int k = 0; k < 128; k++) {
            float av = __half2float(hh[k]) + __half2float(ll[k]);
            const float* wr = sW + k * 16 + q * 4;
#pragma unroll
            for (int j = 0; j < 4; j++) a4[j] = fmaf(av, wr[j], a4[j]);
        }
        float* fo = frac + (size_t)(bm + s) * 16 + q * 4;
#pragma unroll
        for (int j = 0; j < 4; j++)
            fo[j] = __fdividef(1.f, 1.f + __expf(-a4[j]));
    }
}

// ---------------- Sinkhorn: register-resident, 2 threads/sample (R12) ---------
__global__ void __launch_bounds__(256) sinkhorn_reg(
    const float* __restrict__ mat, const float* __restrict__ bids,
    const float* __restrict__ frac, float* __restrict__ outA,
    float* __restrict__ outP)
{
    const int tid = threadIdx.x;
    const int p   = tid & 1;
    const int s   = blockIdx.x * 128 + (tid >> 1);
    const float* mrow = mat + (size_t)s * 256 + p * 8;

    float K[16][8];
#pragma unroll
    for (int i = 0; i < 16; i++) {
        float4 x0 = *(const float4*)(mrow + i * 16);
        float4 x1 = *(const float4*)(mrow + i * 16 + 4);
        K[i][0] = __expf(x0.x * 10.f); K[i][1] = __expf(x0.y * 10.f);
        K[i][2] = __expf(x0.z * 10.f); K[i][3] = __expf(x0.w * 10.f);
        K[i][4] = __expf(x1.x * 10.f); K[i][5] = __expf(x1.y * 10.f);
        K[i][6] = __expf(x1.z * 10.f); K[i][7] = __expf(x1.w * 10.f);
    }

    float v[8], v16 = 1.f;
#pragma unroll
    for (int j = 0; j < 8; j++) v[j] = 1.f;
    float u[16], u16;

#pragma unroll 1
    for (int rnd = 0; rnd < 40; rnd++) {
        float r[17];
#pragma unroll
        for (int i = 0; i < 16; i++) {
            float a = K[i][0] * v[0];
#pragma unroll
            for (int j = 1; j < 8; j++) a = fmaf(K[i][j], v[j], a);
            r[i] = a;
        }
        {
            float a = v[0];
#pragma unroll
            for (int j = 1; j < 8; j++) a += v[j];
            r[16] = a;
        }
#pragma unroll
        for (int i = 0; i < 17; i++)
            r[i] += __shfl_xor_sync(0xFFFFFFFFu, r[i], 1);
#pragma unroll
        for (int i = 0; i < 16; i++) u[i] = __fdividef(1.f, r[i] + v16);
        u16 = __fdividef(16.f, r[16] + v16);

        float usum = u[0];
#pragma unroll
        for (int i = 1; i < 16; i++) usum += u[i];
#pragma unroll
        for (int j = 0; j < 8; j++) {
            float c = u16;
#pragma unroll
            for (int i = 0; i < 16; i++) c = fmaf(K[i][j], u[i], c);
            v[j] = __fdividef(1.f, c);
        }
        v16 = __fdividef(16.f, usum + u16);
    }

    const float* brow = bids + (size_t)s * 256 + p * 8;
    float* arow = outA + (size_t)s * 256 + p * 8;
    float pp[16];
#pragma unroll
    for (int i = 0; i < 16; i++) {
        float4 b0 = *(const float4*)(brow + i * 16);
        float4 b1 = *(const float4*)(brow + i * 16 + 4);
        float ui = u[i];
        float a0 = ui * K[i][0] * v[0], a1 = ui * K[i][1] * v[1];
        float a2 = ui * K[i][2] * v[2], a3 = ui * K[i][3] * v[3];
        float a4 = ui * K[i][4] * v[4], a5 = ui * K[i][5] * v[5];
        float a6 = ui * K[i][6] * v[6], a7 = ui * K[i][7] * v[7];
        *(float4*)(arow + i * 16)     = make_float4(a0, a1, a2, a3);
        *(float4*)(arow + i * 16 + 4) = make_float4(a4, a5, a6, a7);
        pp[i] = a0 * b0.x + a1 * b0.y + a2 * b0.z + a3 * b0.w
              + a4 * b1.x + a5 * b1.y + a6 * b1.z + a7 * b1.w;
    }
#pragma unroll
    for (int i = 0; i < 16; i++)
        pp[i] += __shfl_xor_sync(0xFFFFFFFFu, pp[i], 1);

    const float* frow = frac + (size_t)s * 16 + p * 8;
    float4 f0 = *(const float4*)frow;
    float4 f1 = *(const float4*)(frow + 4);
    float pay[8];
#pragma unroll
    for (int q = 0; q < 8; q++) pay[q] = p ? pp[8 + q] : pp[q];
    pay[0] *= f0.x; pay[1] *= f0.y; pay[2] *= f0.z; pay[3] *= f0.w;
    pay[4] *= f1.x; pay[5] *= f1.y; pay[6] *= f1.z; pay[7] *= f1.w;
    float* prow = outP + (size_t)s * 16 + p * 8;
    *(float4*)prow       = make_float4(pay[0], pay[1], pay[2], pay[3]);
    *(float4*)(prow + 4) = make_float4(pay[4], pay[5], pay[6], pay[7]);
}

// ---------------- launch -----------------------------------------------------
extern "C" void kernel_launch(void* const* d_in, const int* in_sizes, int n_in,
                              void* d_out, int out_size)
{
    const float* bids = (const float*)d_in[0];
    const float* aw0 = (const float*)d_in[1];  const float* ab0 = (const float*)d_in[2];
    const float* aw1 = (const float*)d_in[3];  const float* ab1 = (const float*)d_in[4];
    const float* aw2 = (const float*)d_in[5];  const float* ab2 = (const float*)d_in[6];
    const float* aw3 = (const float*)d_in[7];  const float* ab3 = (const float*)d_in[8];
    const float* pw0 = (const float*)d_in[9];  const float* pb0 = (const float*)d_in[10];
    const float* pw1 = (const float*)d_in[11]; const float* pb1 = (const float*)d_in[12];
    const float* pw2 = (const float*)d_in[13]; const float* pb2 = (const float*)d_in[14];
    const float* pw3 = (const float*)d_in[15]; const float* pb3 = (const float*)d_in[16];

    const int M = in_sizes[0] / 256;  // 32768

    void* p;
    cudaGetSymbolAddress(&p, g_mat);  float* mat = (float*)p;
    cudaGetSymbolAddress(&p, g_frac); float* fr  = (float*)p;
    cudaGetSymbolAddress(&p, g_wt);   __half* wt = (__half*)p;

    cudaFuncSetAttribute(fused_mlp, cudaFuncAttributeMaxDynamicSharedMemorySize,
                         SMEM_BYTES);

    pack_w_tile<<<dim3(32, 7), 256>>>(aw0, aw1, aw2, aw3, pw0, pw1, pw2, wt);

    fused_mlp<<<dim3(M / 64, 2), 256, SMEM_BYTES>>>(
        bids, wt, ab0, ab1, ab2, ab3, pb0, pb1, pb2, pw3, pb3, mat, fr);

    float* out = (float*)d_out;
    sinkhorn_reg<<<M / 128, 256>>>(mat, bids, fr, out, out + (size_t)M * 256);
}

// round 17
// speedup vs baseline: 1.1735x; 1.0248x over previous
#include <cuda_runtime.h>
#include <cuda_fp16.h>
#include <cstdint>
#include <math.h>

// DoubleNet (sm_103, HMMA): R16 winner + f32x2-packed Sinkhorn.
// Layer-fused MLP kernel per net, MUFU tanh, 2-thr/sample Sinkhorn with
// fma.rn.f32x2 packed arithmetic. B=32768, D=256, H=128, A=I=16, EPS=0.1.

#define MAXB 32768

__device__ float  g_mat [MAXB * 256];
__device__ float  g_frac[MAXB * 16];
__device__ __half g_wt[327680];   // per-weight: hi plane [N*K], lo plane [N*K]

#define OFF_AW0 0
#define OFF_AW1 65536
#define OFF_AW2 98304
#define OFF_AW3 131072
#define OFF_PW0 196608
#define OFF_PW1 262144
#define OFF_PW2 294912

// ---------------- helpers ----------------------------------------------------
__device__ __forceinline__ uint32_t smem_u32(const void* p) {
    uint32_t a;
    asm("{ .reg .u64 t; cvta.to.shared.u64 t, %1; cvt.u32.u64 %0, t; }"
        : "=r"(a) : "l"(p));
    return a;
}
__device__ __forceinline__ float ftanh(float x) {
    float e = __expf(2.f * x);
    return 1.f - __fdividef(2.f, e + 1.f);
}
__device__ __forceinline__ void split2(float x0, float x1, uint32_t& hw, uint32_t& lw) {
    __half h0 = __float2half_rn(x0), h1 = __float2half_rn(x1);
    __half l0 = __float2half_rn(x0 - __half2float(h0));
    __half l1 = __float2half_rn(x1 - __half2float(h1));
    hw = (uint32_t)__half_as_ushort(h0) | ((uint32_t)__half_as_ushort(h1) << 16);
    lw = (uint32_t)__half_as_ushort(l0) | ((uint32_t)__half_as_ushort(l1) << 16);
}
__device__ __forceinline__ void mma16816_f(float* d, const uint32_t* a, const uint32_t* b) {
    asm volatile(
        "mma.sync.aligned.m16n8k16.row.col.f32.f16.f16.f32 "
        "{%0,%1,%2,%3}, {%4,%5,%6,%7}, {%8,%9}, {%0,%1,%2,%3};"
        : "+f"(d[0]), "+f"(d[1]), "+f"(d[2]), "+f"(d[3])
        : "r"(a[0]), "r"(a[1]), "r"(a[2]), "r"(a[3]), "r"(b[0]), "r"(b[1]));
}
__device__ __forceinline__ void mma16816_h(uint32_t* d, const uint32_t* a, const uint32_t* b) {
    asm volatile(
        "mma.sync.aligned.m16n8k16.row.col.f16.f16.f16.f16 "
        "{%0,%1}, {%2,%3,%4,%5}, {%6,%7}, {%0,%1};"
        : "+r"(d[0]), "+r"(d[1])
        : "r"(a[0]), "r"(a[1]), "r"(a[2]), "r"(a[3]), "r"(b[0]), "r"(b[1]));
}
#define LDSM4(R, addr) \
    asm volatile("ldmatrix.sync.aligned.m8n8.x4.shared.b16 {%0,%1,%2,%3}, [%4];" \
                 : "=r"((R)[0]), "=r"((R)[1]), "=r"((R)[2]), "=r"((R)[3]) : "r"(addr))
#define CP_ASYNC16(dst, src) \
    asm volatile("cp.async.cg.shared.global [%0], [%1], 16;" :: "r"(dst), "l"(src))
#define CP_COMMIT() asm volatile("cp.async.commit_group;")
#define CP_WAIT0()  asm volatile("cp.async.wait_group 0;")

// ---- f32x2 packed ops (B300 dual-issue FMA; IEEE rn per lane) ----------------
__device__ __forceinline__ uint64_t pk2(float a, float b) {
    uint64_t r; asm("mov.b64 %0, {%1, %2};" : "=l"(r) : "f"(a), "f"(b)); return r;
}
__device__ __forceinline__ void upk2(float& a, float& b, uint64_t v) {
    asm("mov.b64 {%0, %1}, %2;" : "=f"(a), "=f"(b) : "l"(v));
}
__device__ __forceinline__ uint64_t fma2(uint64_t a, uint64_t b, uint64_t c) {
    uint64_t d; asm("fma.rn.f32x2 %0, %1, %2, %3;" : "=l"(d) : "l"(a), "l"(b), "l"(c));
    return d;
}
__device__ __forceinline__ uint64_t mul2(uint64_t a, uint64_t b) {
    uint64_t d; asm("mul.rn.f32x2 %0, %1, %2;" : "=l"(d) : "l"(a), "l"(b));
    return d;
}
__device__ __forceinline__ uint64_t add2(uint64_t a, uint64_t b) {
    uint64_t d; asm("add.rn.f32x2 %0, %1, %2;" : "=l"(d) : "l"(a), "l"(b));
    return d;
}

// ---------------- weight packing: SMEM tile transpose -------------------------
__global__ void pack_w_tile(const float* __restrict__ aw0, const float* __restrict__ aw1,
                            const float* __restrict__ aw2, const float* __restrict__ aw3,
                            const float* __restrict__ pw0, const float* __restrict__ pw1,
                            const float* __restrict__ pw2, __half* __restrict__ wt)
{
    const float* src; int K, N, off;
    switch (blockIdx.y) {
        case 0: src = aw0; K = 256; N = 128; off = OFF_AW0; break;
        case 1: src = aw1; K = 128; N = 128; off = OFF_AW1; break;
        case 2: src = aw2; K = 128; N = 128; off = OFF_AW2; break;
        case 3: src = aw3; K = 128; N = 256; off = OFF_AW3; break;
        case 4: src = pw0; K = 256; N = 128; off = OFF_PW0; break;
        case 5: src = pw1; K = 128; N = 128; off = OFF_PW1; break;
        default: src = pw2; K = 128; N = 128; off = OFF_PW2; break;
    }
    int tiles_n = N / 32;
    int tile = blockIdx.x;
    if (tile >= (K / 32) * tiles_n) return;
    int k0 = (tile / tiles_n) * 32, n0 = (tile % tiles_n) * 32;

    __shared__ float t[32][33];
    int c = threadIdx.x & 31, r8 = threadIdx.x >> 5;
#pragma unroll
    for (int j = 0; j < 4; j++) {
        int r = r8 + j * 8;
        t[r][c] = src[(size_t)(k0 + r) * N + n0 + c];
    }
    __syncthreads();
#pragma unroll
    for (int j = 0; j < 4; j++) {
        int n = r8 + j * 8;
        float v = t[c][n];
        __half h = __float2half_rn(v);
        size_t o = (size_t)(n0 + n) * K + k0 + c;
        wt[off + o]                 = h;
        wt[off + (size_t)N * K + o] = __float2half_rn(v - __half2float(h));
    }
}

// ---------------- SMEM layout ------------------------------------------------
#define ROWB   272
#define APLANE 17408
#define SM_AHI 0
#define SM_ALO 17408
#define SM_BHI 34816
#define SM_BLO 69632
#define SMEM_BYTES 104448

__device__ __forceinline__ void cpa128(uint32_t dst, const __half* __restrict__ src,
                                       int stride_h, int tid) {
#pragma unroll
    for (int j = 0; j < 8; j++) {
        int lin = j * 256 + tid;
        int row = lin >> 4;
        int q   = lin & 15;
        CP_ASYNC16(dst + row * ROWB + q * 16, src + row * stride_h + q * 8);
    }
}
__device__ __forceinline__ void load_w(uint32_t sb, const __half* __restrict__ whi,
                                       const __half* __restrict__ wlo,
                                       int noff, int koff, int K, int tid) {
    cpa128(sb + SM_BHI, whi + (size_t)noff * K + koff, K, tid);
    cpa128(sb + SM_BLO, wlo + (size_t)noff * K + koff, K, tid);
    CP_COMMIT();
}
__device__ __forceinline__ void load_f32_pair(char* hi, char* lo,
                                              const float4* __restrict__ src,
                                              int stride16, int tid) {
#pragma unroll
    for (int j = 0; j < 8; j++) {
        int lin = j * 256 + tid;
        int row = lin >> 5;
        int g   = lin & 31;
        float4 v = src[row * stride16 + g];
        uint32_t h0, l0, h1, l1;
        split2(v.x, v.y, h0, l0);
        split2(v.z, v.w, h1, l1);
        int off = row * ROWB + g * 8;
        *(uint2*)(hi + off) = make_uint2(h0, h1);
        *(uint2*)(lo + off) = make_uint2(l0, l1);
    }
}

// ---------------- MMA tile ----------------------------------------------------
struct Acc {
    float    f[2][4][4];
    uint32_t h[2][4][2];
    __device__ __forceinline__ void zero() {
#pragma unroll
        for (int i = 0; i < 2; i++)
#pragma unroll
            for (int j = 0; j < 4; j++) {
#pragma unroll
                for (int q = 0; q < 4; q++) f[i][j][q] = 0.f;
                h[i][j][0] = 0u; h[i][j][1] = 0u;
            }
    }
    __device__ __forceinline__ void merge() {
#pragma unroll
        for (int i = 0; i < 2; i++)
#pragma unroll
            for (int j = 0; j < 4; j++) {
                float2 f0 = __half22float2(*reinterpret_cast<__half2*>(&h[i][j][0]));
                float2 f1 = __half22float2(*reinterpret_cast<__half2*>(&h[i][j][1]));
                f[i][j][0] += f0.x; f[i][j][1] += f0.y;
                f[i][j][2] += f1.x; f[i][j][3] += f1.y;
            }
    }
};

__device__ __forceinline__ void mma_phase(Acc& A, uint32_t aBase, uint32_t bBase) {
#pragma unroll
    for (int kk = 0; kk < 8; kk++) {
        uint32_t ahi[2][4], alo[2][4];
#pragma unroll
        for (int i = 0; i < 2; i++) {
            LDSM4(ahi[i], aBase + i * (16 * ROWB) + kk * 32);
            LDSM4(alo[i], aBase + APLANE + i * (16 * ROWB) + kk * 32);
        }
        uint32_t bhi[4][2], blo[4][2];
#pragma unroll
        for (int jj = 0; jj < 2; jj++) {
            uint32_t r[4];
            LDSM4(r, bBase + jj * (16 * ROWB) + kk * 32);
            bhi[2 * jj][0] = r[0]; bhi[2 * jj + 1][0] = r[1];
            bhi[2 * jj][1] = r[2]; bhi[2 * jj + 1][1] = r[3];
            LDSM4(r, bBase + 2 * APLANE + jj * (16 * ROWB) + kk * 32);
            blo[2 * jj][0] = r[0]; blo[2 * jj + 1][0] = r[1];
            blo[2 * jj][1] = r[2]; blo[2 * jj + 1][1] = r[3];
        }
#pragma unroll
        for (int j = 0; j < 4; j++)
#pragma unroll
            for (int i = 0; i < 2; i++) {
                mma16816_f(A.f[i][j], ahi[i], bhi[j]);
                mma16816_h(A.h[i][j], ahi[i], blo[j]);
                mma16816_h(A.h[i][j], alo[i], bhi[j]);
            }
    }
}

__device__ __forceinline__ void epilogue_act(Acc& A, const float* __restrict__ bias,
                                             char* smem, int wm, int wn, int lane) {
    const int r4 = lane >> 2;
    uint32_t* stgH = (uint32_t*)(smem + SM_AHI);
    uint32_t* stgL = (uint32_t*)(smem + SM_ALO);
#pragma unroll
    for (int i = 0; i < 2; i++) {
        int r0 = wm + i * 16 + r4;
#pragma unroll
        for (int j = 0; j < 4; j++) {
            int c0 = wn + j * 8 + (lane & 3) * 2;
            float b0 = bias[c0], b1 = bias[c0 + 1];
            uint32_t hw, lw;
            split2(ftanh(A.f[i][j][0] + b0), ftanh(A.f[i][j][1] + b1), hw, lw);
            stgH[r0 * 68 + (c0 >> 1)] = hw;
            stgL[r0 * 68 + (c0 >> 1)] = lw;
            split2(ftanh(A.f[i][j][2] + b0), ftanh(A.f[i][j][3] + b1), hw, lw);
            stgH[(r0 + 8) * 68 + (c0 >> 1)] = hw;
            stgL[(r0 + 8) * 68 + (c0 >> 1)] = lw;
        }
    }
}

// ---------------- fused 4-layer MLP (R16 structure, unchanged) ----------------
__global__ void __launch_bounds__(256, 2)
fused_mlp(const float* __restrict__ bids, const __half* __restrict__ wt,
          const float* __restrict__ ab0, const float* __restrict__ ab1,
          const float* __restrict__ ab2, const float* __restrict__ ab3,
          const float* __restrict__ pb0, const float* __restrict__ pb1,
          const float* __restrict__ pb2,
          const float* __restrict__ pw3, const float* __restrict__ pb3,
          float* __restrict__ mat, float* __restrict__ frac)
{
    extern __shared__ __align__(16) char smem[];
    const int tid  = threadIdx.x;
    const int lane = tid & 31;
    const int w    = tid >> 5;
    const int wm   = (w & 1) * 32;
    const int wn   = (w >> 1) * 32;
    const int bm   = blockIdx.x * 64;
    const bool pay = blockIdx.y != 0;

    const uint32_t sb = smem_u32(smem);
    const int l15 = lane & 15;
    const int lhi = (lane >> 4) * 16;
    const uint32_t aBase = sb + SM_AHI + (uint32_t)(wm + l15) * ROWB + lhi;
    const uint32_t bBase = sb + SM_BHI + (uint32_t)(wn + l15) * ROWB + lhi;

    const __half* w0h = wt + (pay ? OFF_PW0 : OFF_AW0);
    const __half* w1h = wt + (pay ? OFF_PW1 : OFF_AW1);
    const __half* w2h = wt + (pay ? OFF_PW2 : OFF_AW2);
    const float* b0 = pay ? pb0 : ab0;
    const float* b1 = pay ? pb1 : ab1;
    const float* b2 = pay ? pb2 : ab2;

    Acc acc;

    acc.zero();
#pragma unroll 1
    for (int c = 0; c < 2; c++) {
        load_w(sb, w0h, w0h + 32768, 0, c * 128, 256, tid);
        load_f32_pair(smem + SM_AHI, smem + SM_ALO,
                      (const float4*)(bids + (size_t)bm * 256 + c * 128), 64, tid);
        CP_WAIT0(); __syncthreads();
        mma_phase(acc, aBase, bBase);
        __syncthreads();
    }
    load_w(sb, w1h, w1h + 16384, 0, 0, 128, tid);
    acc.merge();
    epilogue_act(acc, b0, smem, wm, wn, lane);
    CP_WAIT0(); __syncthreads();

    acc.zero();
    mma_phase(acc, aBase, bBase);
    __syncthreads();
    load_w(sb, w2h, w2h + 16384, 0, 0, 128, tid);
    acc.merge();
    epilogue_act(acc, b1, smem, wm, wn, lane);
    CP_WAIT0(); __syncthreads();

    acc.zero();
    mma_phase(acc, aBase, bBase);
    __syncthreads();
    if (!pay)
        load_w(sb, wt + OFF_AW3, wt + OFF_AW3 + 32768, 0, 0, 128, tid);
    acc.merge();
    epilogue_act(acc, b2, smem, wm, wn, lane);
    CP_WAIT0(); __syncthreads();

    if (!pay) {
#pragma unroll 1
        for (int h = 0; h < 2; h++) {
            acc.zero();
            mma_phase(acc, aBase, bBase);
            __syncthreads();
            acc.merge();
            float* stage = (float*)(smem + SM_BHI);
            const int r4 = lane >> 2;
#pragma unroll
            for (int i = 0; i < 2; i++) {
                int r0 = wm + i * 16 + r4;
#pragma unroll
                for (int j = 0; j < 4; j++) {
                    int c0 = wn + j * 8 + (lane & 3) * 2;
                    float bb0 = ab3[h * 128 + c0], bb1 = ab3[h * 128 + c0 + 1];
                    stage[r0 * 132 + c0]           = acc.f[i][j][0] + bb0;
                    stage[r0 * 132 + c0 + 1]       = acc.f[i][j][1] + bb1;
                    stage[(r0 + 8) * 132 + c0]     = acc.f[i][j][2] + bb0;
                    stage[(r0 + 8) * 132 + c0 + 1] = acc.f[i][j][3] + bb1;
                }
            }
            __syncthreads();
            float* og = mat + (size_t)bm * 256 + h * 128;
#pragma unroll
            for (int it = 0; it < 32; it++) {
                int lin = it * 256 + tid;
                int row = lin >> 7, col = lin & 127;
                og[row * 256 + col] = stage[row * 132 + col];
            }
            if (h == 0) {
                __syncthreads();
                load_w(sb, wt + OFF_AW3, wt + OFF_AW3 + 32768, 128, 0, 128, tid);
                CP_WAIT0(); __syncthreads();
            }
        }
    } else {
        float* sW = (float*)(smem + SM_BHI);
#pragma unroll
        for (int t = 0; t < 8; t++) sW[t * 256 + tid] = pw3[t * 256 + tid];
        __syncthreads();
        const int s = tid >> 2, q = tid & 3;
        const __half* hh = (const __half*)(smem + SM_AHI) + s * 136;
        const __half* ll = (const __half*)(smem + SM_ALO) + s * 136;
        float a4[4];
#pragma unroll
        for (int j = 0; j < 4; j++) a4[j] = pb3[q * 4 + j];
#pragma unroll 8
        for (int k = 0; k < 128; k++) {
            float av = __half2float(hh[k]) + __half2float(ll[k]);
            const float* wr = sW + k * 16 + q * 4;
#pragma unroll
            for (int j = 0; j < 4; j++) a4[j] = fmaf(av, wr[j], a4[j]);
        }
        float* fo = frac + (size_t)(bm + s) * 16 + q * 4;
#pragma unroll
        for (int j = 0; j < 4; j++)
            fo[j] = __fdividef(1.f, 1.f + __expf(-a4[j]));
    }
}

// ---------------- Sinkhorn: 2 thr/sample, f32x2-packed ------------------------
// Thread parity p owns columns [8p, 8p+8) packed as 4 f32x2 lanes.
__global__ void __launch_bounds__(256) sinkhorn_reg(
    const float* __restrict__ mat, const float* __restrict__ bids,
    const float* __restrict__ frac, float* __restrict__ outA,
    float* __restrict__ outP)
{
    const int tid = threadIdx.x;
    const int p   = tid & 1;
    const int s   = blockIdx.x * 128 + (tid >> 1);
    const float* mrow = mat + (size_t)s * 256 + p * 8;

    uint64_t Kp[16][4];
#pragma unroll
    for (int i = 0; i < 16; i++) {
        float4 x0 = *(const float4*)(mrow + i * 16);
        float4 x1 = *(const float4*)(mrow + i * 16 + 4);
        Kp[i][0] = pk2(__expf(x0.x * 10.f), __expf(x0.y * 10.f));
        Kp[i][1] = pk2(__expf(x0.z * 10.f), __expf(x0.w * 10.f));
        Kp[i][2] = pk2(__expf(x1.x * 10.f), __expf(x1.y * 10.f));
        Kp[i][3] = pk2(__expf(x1.z * 10.f), __expf(x1.w * 10.f));
    }

    uint64_t vp[4];
    const uint64_t ONE2 = pk2(1.f, 1.f);
#pragma unroll
    for (int t = 0; t < 4; t++) vp[t] = ONE2;
    float v16 = 1.f;
    float u[16], u16;

#pragma unroll 1
    for (int rnd = 0; rnd < 40; rnd++) {
        // row pass (packed partials over own 8 columns)
        float r[17];
#pragma unroll
        for (int i = 0; i < 16; i++) {
            uint64_t a = mul2(Kp[i][0], vp[0]);
            a = fma2(Kp[i][1], vp[1], a);
            a = fma2(Kp[i][2], vp[2], a);
            a = fma2(Kp[i][3], vp[3], a);
            float lo, hi; upk2(lo, hi, a);
            r[i] = lo + hi;
        }
        {
            uint64_t sv = add2(add2(vp[0], vp[1]), add2(vp[2], vp[3]));
            float lo, hi; upk2(lo, hi, sv);
            r[16] = lo + hi;
        }
#pragma unroll
        for (int i = 0; i < 17; i++)
            r[i] += __shfl_xor_sync(0xFFFFFFFFu, r[i], 1);
#pragma unroll
        for (int i = 0; i < 16; i++) u[i] = __fdividef(1.f, r[i] + v16);
        u16 = __fdividef(16.f, r[16] + v16);

        float usum = u[0];
#pragma unroll
        for (int i = 1; i < 16; i++) usum += u[i];

        // col pass (packed; thread-local)
        uint64_t u2[16];
#pragma unroll
        for (int i = 0; i < 16; i++) u2[i] = pk2(u[i], u[i]);
#pragma unroll
        for (int t = 0; t < 4; t++) {
            uint64_t c = mul2(Kp[0][t], u2[0]);
#pragma unroll
            for (int i = 1; i < 16; i++) c = fma2(Kp[i][t], u2[i], c);
            float c0, c1; upk2(c0, c1, c);
            vp[t] = pk2(__fdividef(1.f, c0 + u16), __fdividef(1.f, c1 + u16));
        }
        v16 = __fdividef(16.f, usum + u16);
    }

    // epilogue: allocs (own 8 cols, packed) + fused payments
    const float* brow = bids + (size_t)s * 256 + p * 8;
    float* arow = outA + (size_t)s * 256 + p * 8;
    float pp[16];
#pragma unroll
    for (int i = 0; i < 16; i++) {
        uint64_t ui2 = pk2(u[i], u[i]);
        uint64_t ap0 = mul2(mul2(Kp[i][0], vp[0]), ui2);
        uint64_t ap1 = mul2(mul2(Kp[i][1], vp[1]), ui2);
        uint64_t ap2 = mul2(mul2(Kp[i][2], vp[2]), ui2);
        uint64_t ap3 = mul2(mul2(Kp[i][3], vp[3]), ui2);
        float a0, a1, a2, a3, a4, a5, a6, a7;
        upk2(a0, a1, ap0); upk2(a2, a3, ap1);
        upk2(a4, a5, ap2); upk2(a6, a7, ap3);
        *(float4*)(arow + i * 16)     = make_float4(a0, a1, a2, a3);
        *(float4*)(arow + i * 16 + 4) = make_float4(a4, a5, a6, a7);
        float4 b0 = *(const float4*)(brow + i * 16);
        float4 b1 = *(const float4*)(brow + i * 16 + 4);
        pp[i] = a0 * b0.x + a1 * b0.y + a2 * b0.z + a3 * b0.w
              + a4 * b1.x + a5 * b1.y + a6 * b1.z + a7 * b1.w;
    }
#pragma unroll
    for (int i = 0; i < 16; i++)
        pp[i] += __shfl_xor_sync(0xFFFFFFFFu, pp[i], 1);

    const float* frow = frac + (size_t)s * 16 + p * 8;
    float4 f0 = *(const float4*)frow;
    float4 f1 = *(const float4*)(frow + 4);
    float pay[8];
#pragma unroll
    for (int q = 0; q < 8; q++) pay[q] = p ? pp[8 + q] : pp[q];
    pay[0] *= f0.x; pay[1] *= f0.y; pay[2] *= f0.z; pay[3] *= f0.w;
    pay[4] *= f1.x; pay[5] *= f1.y; pay[6] *= f1.z; pay[7] *= f1.w;
    float* prow = outP + (size_t)s * 16 + p * 8;
    *(float4*)prow       = make_float4(pay[0], pay[1], pay[2], pay[3]);
    *(float4*)(prow + 4) = make_float4(pay[4], pay[5], pay[6], pay[7]);
}

// ---------------- launch -----------------------------------------------------
extern "C" void kernel_launch(void* const* d_in, const int* in_sizes, int n_in,
                              void* d_out, int out_size)
{
    const float* bids = (const float*)d_in[0];
    const float* aw0 = (const float*)d_in[1];  const float* ab0 = (const float*)d_in[2];
    const float* aw1 = (const float*)d_in[3];  const float* ab1 = (const float*)d_in[4];
    const float* aw2 = (const float*)d_in[5];  const float* ab2 = (const float*)d_in[6];
    const float* aw3 = (const float*)d_in[7];  const float* ab3 = (const float*)d_in[8];
    const float* pw0 = (const float*)d_in[9];  const float* pb0 = (const float*)d_in[10];
    const float* pw1 = (const float*)d_in[11]; const float* pb1 = (const float*)d_in[12];
    const float* pw2 = (const float*)d_in[13]; const float* pb2 = (const float*)d_in[14];
    const float* pw3 = (const float*)d_in[15]; const float* pb3 = (const float*)d_in[16];

    const int M = in_sizes[0] / 256;  // 32768

    void* p;
    cudaGetSymbolAddress(&p, g_mat);  float* mat = (float*)p;
    cudaGetSymbolAddress(&p, g_frac); float* fr  = (float*)p;
    cudaGetSymbolAddress(&p, g_wt);   __half* wt = (__half*)p;

    cudaFuncSetAttribute(fused_mlp, cudaFuncAttributeMaxDynamicSharedMemorySize,
                         SMEM_BYTES);

    pack_w_tile<<<dim3(32, 7), 256>>>(aw0, aw1, aw2, aw3, pw0, pw1, pw2, wt);

    fused_mlp<<<dim3(M / 64, 2), 256, SMEM_BYTES>>>(
        bids, wt, ab0, ab1, ab2, ab3, pb0, pb1, pb2, pw3, pb3, mat, fr);

    float* out = (float*)d_out;
    sinkhorn_reg<<<M / 128, 256>>>(mat, bids, fr, out, out + (size_t)M * 256);
}